// round 3
// baseline (speedup 1.0000x reference)
#include <cuda_runtime.h>

// ---------------------------------------------------------------------------
// Linear SSM y_t = C h_t + D x_t, h_t = A h_{t-1} + B x_t
// Implemented as a truncated causal convolution with kernels K_d = C A^d B,
// d = 0..DMAX-1 (DMAX=112; tail ~0.9^112 ~ 8e-6 rel, << 1e-3 tolerance).
// K_0 additionally absorbs D.
//
// Stage 1 (fp32 CUDA-core GEMM chain, ~14 graph nodes):
//   powers A^2..A^64 (doubling), W_{d1}=C*A^{d1} for d1=0..15 (stack doubling),
//   V_j = A^{16j}*B for j=0..6 (stacked), K_d = W_{d&15} * V_{d>>4}.
// Stage 2: conv kernel, K-bank staged through smem (double buffered),
//   x window staged transposed in smem, 4o x 8t register tile per thread.
// ---------------------------------------------------------------------------

#define SEQ   4096
#define BATCH 16
#define DIN   64
#define DOUT  64
#define NST   512
#define DMAX  112
#define TN    128        // t-tile per CTA
#define XR    240        // smem x-window rows: TN + DMAX - 1 = 239, padded
#define VW    448        // V cat width = 7 * 64

// scratch: powers(6*262144) + Wcat(1024*512) + Vcat(512*448) + Kt(112*4096)
#define OFF_P2   0
#define OFF_P4   262144
#define OFF_P8   524288
#define OFF_P16  786432
#define OFF_P32  1048576
#define OFF_P64  1310720
#define OFF_W    1572864
#define OFF_V    2097152
#define OFF_K    2326528
#define SCRATCH_FLOATS 2785280

__device__ float g_scratch[SCRATCH_FLOATS];

// ---------------------------------------------------------------------------
// Generic fp32 GEMM: C[M,N] = A[M,K] * B[K,N], row-major, leading dims given.
// All of M,N multiples of 64; K multiple of 16. Tile 64x64, 256 thr, 4x4 micro.
// ---------------------------------------------------------------------------
__global__ __launch_bounds__(256) void gemm_f32(
    const float* __restrict__ A, const float* __restrict__ B, float* __restrict__ C,
    int M, int N, int K, int lda, int ldb, int ldc)
{
    __shared__ float As[16][68];
    __shared__ float Bs[16][68];
    const int tid = threadIdx.x;
    const int m0 = blockIdx.y * 64, n0 = blockIdx.x * 64;
    const int tn = tid & 15, tm = tid >> 4;
    const int la_m = (tid * 4) >> 4;
    const int la_k = (tid * 4) & 15;
    const int lb_k = (tid * 4) >> 6;
    const int lb_n = (tid * 4) & 63;
    float acc[4][4] = {};

    for (int k0 = 0; k0 < K; k0 += 16) {
        float4 av = *(const float4*)(A + (size_t)(m0 + la_m) * lda + (k0 + la_k));
        As[la_k + 0][la_m] = av.x;
        As[la_k + 1][la_m] = av.y;
        As[la_k + 2][la_m] = av.z;
        As[la_k + 3][la_m] = av.w;
        float4 bv = *(const float4*)(B + (size_t)(k0 + lb_k) * ldb + (n0 + lb_n));
        *(float4*)&Bs[lb_k][lb_n] = bv;
        __syncthreads();
        #pragma unroll
        for (int kk = 0; kk < 16; kk++) {
            float4 a = *(const float4*)&As[kk][tm * 4];
            float4 b = *(const float4*)&Bs[kk][tn * 4];
            acc[0][0] += a.x * b.x; acc[0][1] += a.x * b.y; acc[0][2] += a.x * b.z; acc[0][3] += a.x * b.w;
            acc[1][0] += a.y * b.x; acc[1][1] += a.y * b.y; acc[1][2] += a.y * b.z; acc[1][3] += a.y * b.w;
            acc[2][0] += a.z * b.x; acc[2][1] += a.z * b.y; acc[2][2] += a.z * b.z; acc[2][3] += a.z * b.w;
            acc[3][0] += a.w * b.x; acc[3][1] += a.w * b.y; acc[3][2] += a.w * b.z; acc[3][3] += a.w * b.w;
        }
        __syncthreads();
    }
    #pragma unroll
    for (int r = 0; r < 4; r++) {
        float4 o = make_float4(acc[r][0], acc[r][1], acc[r][2], acc[r][3]);
        *(float4*)(C + (size_t)(m0 + tm * 4 + r) * ldc + (n0 + tn * 4)) = o;
    }
}

// ---------------------------------------------------------------------------
// K_d = W_{d&15} * V_{d>>4}  (+ D for d==0), written TRANSPOSED as Kt[d][i][o]
// One CTA per tap d. M=N=64, K=512.
// ---------------------------------------------------------------------------
__global__ __launch_bounds__(256) void k_assemble(const float* __restrict__ Dm)
{
    const float* Wc = g_scratch + OFF_W;
    const float* Vc = g_scratch + OFF_V;
    float* Kt = g_scratch + OFF_K;
    const int d = blockIdx.x;
    const int d1 = d & 15, j = d >> 4;
    const float* A = Wc + (size_t)d1 * 64 * NST;   // [64 x 512], lda = 512
    const float* B = Vc + j * 64;                  // cols j*64..j*64+63, ldb = VW

    __shared__ float As[16][68];
    __shared__ float Bs[16][68];
    const int tid = threadIdx.x;
    const int tn = tid & 15, tm = tid >> 4;
    const int la_m = (tid * 4) >> 4;
    const int la_k = (tid * 4) & 15;
    const int lb_k = (tid * 4) >> 6;
    const int lb_n = (tid * 4) & 63;
    float acc[4][4] = {};

    for (int k0 = 0; k0 < NST; k0 += 16) {
        float4 av = *(const float4*)(A + (size_t)la_m * NST + (k0 + la_k));
        As[la_k + 0][la_m] = av.x;
        As[la_k + 1][la_m] = av.y;
        As[la_k + 2][la_m] = av.z;
        As[la_k + 3][la_m] = av.w;
        float4 bv = *(const float4*)(B + (size_t)(k0 + lb_k) * VW + lb_n);
        *(float4*)&Bs[lb_k][lb_n] = bv;
        __syncthreads();
        #pragma unroll
        for (int kk = 0; kk < 16; kk++) {
            float4 a = *(const float4*)&As[kk][tm * 4];
            float4 b = *(const float4*)&Bs[kk][tn * 4];
            acc[0][0] += a.x * b.x; acc[0][1] += a.x * b.y; acc[0][2] += a.x * b.z; acc[0][3] += a.x * b.w;
            acc[1][0] += a.y * b.x; acc[1][1] += a.y * b.y; acc[1][2] += a.y * b.z; acc[1][3] += a.y * b.w;
            acc[2][0] += a.z * b.x; acc[2][1] += a.z * b.y; acc[2][2] += a.z * b.z; acc[2][3] += a.z * b.w;
            acc[3][0] += a.w * b.x; acc[3][1] += a.w * b.y; acc[3][2] += a.w * b.z; acc[3][3] += a.w * b.w;
        }
        __syncthreads();
    }
    float* out = Kt + (size_t)d * 4096;
    #pragma unroll
    for (int r = 0; r < 4; r++) {
        #pragma unroll
        for (int c = 0; c < 4; c++) {
            int o = tm * 4 + r, i = tn * 4 + c;
            float v = acc[r][c];
            if (d == 0) v += Dm[o * DIN + i];
            out[i * 64 + o] = v;   // transposed: [i][o] for conv smem loads
        }
    }
}

// ---------------------------------------------------------------------------
// Causal conv: y[b,t,o] = sum_{d<DMAX} sum_i Kt[d][i][o] * x[b,t-d,i]
// CTA = (t-tile of TN, batch). x window transposed in smem [i][row],
// K tap double-buffered (2 x 16KB). Thread: 4 o x 8 t register tile.
// ---------------------------------------------------------------------------
__global__ __launch_bounds__(256) void conv_f32(const float* __restrict__ x,
                                                float* __restrict__ y)
{
    extern __shared__ float sm[];
    float* xs = sm;                 // [DIN][XR]
    float* ks = sm + DIN * XR;      // [2][64*64]
    const float* Kt = g_scratch + OFF_K;
    const int b = blockIdx.y;
    const int t0 = blockIdx.x * TN;
    const int tid = threadIdx.x;

    // stage x window rows t0-(DMAX-1) .. t0+TN-1 (transposed, zeros for t<0)
    for (int r = tid; r < XR; r += 256) {
        int tg = t0 - (DMAX - 1) + r;
        if (r < TN + DMAX - 1 && tg >= 0) {
            const float4* src = (const float4*)(x + ((size_t)b * SEQ + tg) * DIN);
            #pragma unroll
            for (int iv = 0; iv < 16; iv++) {
                float4 v = src[iv];
                xs[(iv * 4 + 0) * XR + r] = v.x;
                xs[(iv * 4 + 1) * XR + r] = v.y;
                xs[(iv * 4 + 2) * XR + r] = v.z;
                xs[(iv * 4 + 3) * XR + r] = v.w;
            }
        } else {
            #pragma unroll
            for (int i = 0; i < DIN; i++) xs[i * XR + r] = 0.f;
        }
    }
    // preload tap 0
    {
        const float4* src = (const float4*)Kt;
        float4* dst = (float4*)ks;
        #pragma unroll
        for (int u = 0; u < 4; u++) dst[tid + 256 * u] = src[tid + 256 * u];
    }
    __syncthreads();

    const int o0 = (tid & 15) * 4;
    const int tb = (tid >> 4) * 8;
    float acc[8][4];
    #pragma unroll
    for (int tt = 0; tt < 8; tt++) {
        acc[tt][0] = 0.f; acc[tt][1] = 0.f; acc[tt][2] = 0.f; acc[tt][3] = 0.f;
    }

    for (int d = 0; d < DMAX; d++) {
        const int cur = d & 1;
        float4 pf[4];
        if (d + 1 < DMAX) {
            const float4* src = (const float4*)(Kt + (size_t)(d + 1) * 4096);
            #pragma unroll
            for (int u = 0; u < 4; u++) pf[u] = src[tid + 256 * u];
        }
        const float* kb = ks + cur * 4096;
        const float* xb = xs + (tb + (DMAX - 1) - d);
        #pragma unroll 8
        for (int i = 0; i < DIN; i++) {
            float4 kv = *(const float4*)(kb + i * 64 + o0);
            const float* xp = xb + i * XR;
            #pragma unroll
            for (int tt = 0; tt < 8; tt++) {
                float xv = xp[tt];
                acc[tt][0] += kv.x * xv;
                acc[tt][1] += kv.y * xv;
                acc[tt][2] += kv.z * xv;
                acc[tt][3] += kv.w * xv;
            }
        }
        if (d + 1 < DMAX) {
            float4* dst = (float4*)(ks + (cur ^ 1) * 4096);
            #pragma unroll
            for (int u = 0; u < 4; u++) dst[tid + 256 * u] = pf[u];
        }
        __syncthreads();
    }

    #pragma unroll
    for (int tt = 0; tt < 8; tt++) {
        int t = t0 + tb + tt;
        float4 o = make_float4(acc[tt][0], acc[tt][1], acc[tt][2], acc[tt][3]);
        *(float4*)(y + ((size_t)b * SEQ + t) * DOUT + o0) = o;
    }
}

// ---------------------------------------------------------------------------
extern "C" void kernel_launch(void* const* d_in, const int* in_sizes, int n_in,
                              void* d_out, int out_size)
{
    const float* x  = (const float*)d_in[0];
    const float* A  = (const float*)d_in[1];
    const float* Bm = (const float*)d_in[2];
    const float* Cm = (const float*)d_in[3];
    const float* Dm = (const float*)d_in[4];
    float* y = (float*)d_out;

    float* s = nullptr;
    cudaGetSymbolAddress((void**)&s, g_scratch);
    float* P2  = s + OFF_P2;
    float* P4  = s + OFF_P4;
    float* P8  = s + OFF_P8;
    float* P16 = s + OFF_P16;
    float* P32 = s + OFF_P32;
    float* P64 = s + OFF_P64;
    float* W   = s + OFF_W;
    float* V   = s + OFF_V;

    const size_t convSmem = (size_t)(DIN * XR + 2 * 4096) * sizeof(float);
    cudaFuncSetAttribute(conv_f32, cudaFuncAttributeMaxDynamicSharedMemorySize,
                         (int)convSmem);

    // W row-block 0 <- C ; V col-block 0 <- B
    cudaMemcpyAsync(W, Cm, (size_t)64 * NST * sizeof(float), cudaMemcpyDeviceToDevice);
    cudaMemcpy2DAsync(V, VW * sizeof(float), Bm, 64 * sizeof(float),
                      64 * sizeof(float), NST, cudaMemcpyDeviceToDevice);

    dim3 thr(256);
    // powers A^2 .. A^64 (doubling)
    gemm_f32<<<dim3(8, 8), thr>>>(A,   A,   P2,  512, 512, 512, 512, 512, 512);
    gemm_f32<<<dim3(8, 8), thr>>>(P2,  P2,  P4,  512, 512, 512, 512, 512, 512);
    gemm_f32<<<dim3(8, 8), thr>>>(P4,  P4,  P8,  512, 512, 512, 512, 512, 512);
    gemm_f32<<<dim3(8, 8), thr>>>(P8,  P8,  P16, 512, 512, 512, 512, 512, 512);
    gemm_f32<<<dim3(8, 8), thr>>>(P16, P16, P32, 512, 512, 512, 512, 512, 512);
    gemm_f32<<<dim3(8, 8), thr>>>(P32, P32, P64, 512, 512, 512, 512, 512, 512);
    // W stack: W_d = C A^d, d = 0..15   (rows [d*64, d*64+64))
    gemm_f32<<<dim3(8, 1), thr>>>(W, A,  W + (size_t)64  * 512,  64, 512, 512, 512, 512, 512);
    gemm_f32<<<dim3(8, 2), thr>>>(W, P2, W + (size_t)128 * 512, 128, 512, 512, 512, 512, 512);
    gemm_f32<<<dim3(8, 4), thr>>>(W, P4, W + (size_t)256 * 512, 256, 512, 512, 512, 512, 512);
    gemm_f32<<<dim3(8, 8), thr>>>(W, P8, W + (size_t)512 * 512, 512, 512, 512, 512, 512, 512);
    // V stack: V_j = A^{16j} B, j = 0..6  (col blocks of width 64 in Vcat)
    gemm_f32<<<dim3(1, 8), thr>>>(P16, V, V + 64,  512,  64, 512, 512, VW, VW);
    gemm_f32<<<dim3(2, 8), thr>>>(P32, V, V + 128, 512, 128, 512, 512, VW, VW);
    gemm_f32<<<dim3(3, 8), thr>>>(P64, V, V + 256, 512, 192, 512, 512, VW, VW);
    // tap bank K_d (transposed) with D folded into K_0
    k_assemble<<<DMAX, thr>>>(Dm);
    // main convolution
    conv_f32<<<dim3(SEQ / TN, BATCH), thr, convSmem>>>(x, y);
}

// round 5
// speedup vs baseline: 3.5572x; 3.5572x over previous
#include <cuda_runtime.h>
#include <cuda_bf16.h>
#include <cstdint>

// ---------------------------------------------------------------------------
// Linear SSM as truncated causal conv: y[t] = sum_{d<112} K_d x[t-d], K_0+=D.
// Stage 1: fp32 split-K GEMM chain builds K_d = C A^d B (tf32-rounded bank).
// Stage 2: mma.sync m16n8k8 tf32 conv (sm_103 non-'a': no tcgen05 available).
//          X window in smem (stride 68, conflict-free A frags), K taps
//          streamed via cp.async.bulk + 4-stage mbarrier ring (stride 72,
//          conflict-free B frags). Toeplitz tap shift = A-frag row offset.
// ---------------------------------------------------------------------------

#define SEQ   4096
#define BATCH 16
#define DIN   64
#define NST   512
#define DMAX  112
#define TM    128
#define VW    448

#define XSTR  68            // X smem row stride (floats)
#define KSTR  72            // K tap row stride (floats)
#define TAPF  4608          // floats per tap  (64*72)
#define TAPB  18432         // bytes per tap
#define NSTG  4

#define SM_X    0
#define SM_K    65280       // 240*68*4
#define SM_BAR  139008      // 65280 + 4*18432
#define SM_TOTAL 139136

// fp32 scratch for stage 1
#define OFF_P2   0
#define OFF_P4   262144
#define OFF_P8   524288
#define OFF_P16  786432
#define OFF_P32  1048576
#define OFF_P64  1310720
#define OFF_W    1572864
#define OFF_V    2097152
#define OFF_SLAB 2326528
#define SCRATCH_FLOATS 3375104
__device__ float g_scratch[SCRATCH_FLOATS];

// tf32-rounded tap bank: g_K[d*TAPF + i*KSTR + o]
__device__ float g_K[DMAX * TAPF];

// ---------------- PTX helpers ----------------
__device__ __forceinline__ uint32_t smem_u32(const void* p) {
    uint32_t a;
    asm("{ .reg .u64 t; cvta.to.shared.u64 t, %1; cvt.u32.u64 %0, t; }"
        : "=r"(a) : "l"(p));
    return a;
}
#define MBAR_INIT(addr, cnt) \
    asm volatile("mbarrier.init.shared.b64 [%0], %1;" :: "r"(addr), "r"(cnt) : "memory")
#define MBAR_EXPECT_TX(addr, bytes) \
    asm volatile("mbarrier.arrive.expect_tx.shared.b64 _, [%0], %1;" :: "r"(addr), "r"(bytes) : "memory")
#define MBAR_ARRIVE(addr) \
    asm volatile("mbarrier.arrive.release.cta.shared.b64 _, [%0];" :: "r"(addr) : "memory")
#define MBAR_WAIT(addr, par) do { \
    uint32_t _m = (addr), _p = (par), _d; \
    asm volatile("{\n\t.reg .pred p;\n\t" \
        "mbarrier.try_wait.parity.acquire.cta.shared::cta.b64 p, [%1], %2;\n\t" \
        "selp.b32 %0, 1, 0, p;\n\t}" : "=r"(_d) : "r"(_m), "r"(_p) : "memory"); \
    if (!_d) { \
        asm volatile("{\n\t.reg .pred P1;\n\t" \
            "WL_%=:\n\t" \
            "mbarrier.try_wait.parity.acquire.cta.shared::cta.b64 P1, [%0], %1, 0x989680;\n\t" \
            "@P1 bra.uni WD_%=;\n\t" \
            "bra.uni WL_%=;\n\t" \
            "WD_%=:\n\t}" :: "r"(_m), "r"(_p) : "memory"); \
    } \
} while (0)
__device__ __forceinline__ void bulk_g2s(uint32_t dst, const void* src,
                                         uint32_t bytes, uint32_t mbar) {
    asm volatile("cp.async.bulk.shared::cta.global.mbarrier::complete_tx::bytes "
        "[%0], [%1], %2, [%3];" :: "r"(dst), "l"(src), "r"(bytes), "r"(mbar) : "memory");
}
__device__ __forceinline__ float tf32r(float v) {
    float r;
    asm("cvt.rna.tf32.f32 %0, %1;" : "=f"(r) : "f"(v));
    return r;
}
__device__ __forceinline__ void mma_tf32(float* c, uint32_t a0, uint32_t a1,
                                         uint32_t a2, uint32_t a3,
                                         uint32_t b0, uint32_t b1) {
    asm volatile("mma.sync.aligned.m16n8k8.row.col.f32.tf32.tf32.f32 "
        "{%0,%1,%2,%3}, {%4,%5,%6,%7}, {%8,%9}, {%0,%1,%2,%3};"
        : "+f"(c[0]), "+f"(c[1]), "+f"(c[2]), "+f"(c[3])
        : "r"(a0), "r"(a1), "r"(a2), "r"(a3), "r"(b0), "r"(b1));
}

// ---------------------------------------------------------------------------
// fp32 split-K GEMM: slab z computes A[:,zKc:(z+1)Kc] * B[zKc:(z+1)Kc,:]
// into out + z*M*N (dense). Tile 64x64, 256 thr, 4x4 micro.
// ---------------------------------------------------------------------------
__global__ __launch_bounds__(256) void gemm_sk(
    const float* __restrict__ A, const float* __restrict__ B, float* __restrict__ out,
    int M, int N, int Kc, int lda, int ldb)
{
    A += (size_t)blockIdx.z * Kc;
    B += (size_t)blockIdx.z * Kc * ldb;
    out += (size_t)blockIdx.z * M * N;
    __shared__ float As[16][68];
    __shared__ float Bs[16][68];
    const int tid = threadIdx.x;
    const int m0 = blockIdx.y * 64, n0 = blockIdx.x * 64;
    const int tn = tid & 15, tm = tid >> 4;
    const int la_m = (tid * 4) >> 4;
    const int la_k = (tid * 4) & 15;
    const int lb_k = (tid * 4) >> 6;
    const int lb_n = (tid * 4) & 63;
    float acc[4][4] = {};

    for (int k0 = 0; k0 < Kc; k0 += 16) {
        float4 av = *(const float4*)(A + (size_t)(m0 + la_m) * lda + (k0 + la_k));
        As[la_k + 0][la_m] = av.x; As[la_k + 1][la_m] = av.y;
        As[la_k + 2][la_m] = av.z; As[la_k + 3][la_m] = av.w;
        float4 bv = *(const float4*)(B + (size_t)(k0 + lb_k) * ldb + (n0 + lb_n));
        *(float4*)&Bs[lb_k][lb_n] = bv;
        __syncthreads();
        #pragma unroll
        for (int kk = 0; kk < 16; kk++) {
            float4 a = *(const float4*)&As[kk][tm * 4];
            float4 b = *(const float4*)&Bs[kk][tn * 4];
            acc[0][0] += a.x * b.x; acc[0][1] += a.x * b.y; acc[0][2] += a.x * b.z; acc[0][3] += a.x * b.w;
            acc[1][0] += a.y * b.x; acc[1][1] += a.y * b.y; acc[1][2] += a.y * b.z; acc[1][3] += a.y * b.w;
            acc[2][0] += a.z * b.x; acc[2][1] += a.z * b.y; acc[2][2] += a.z * b.z; acc[2][3] += a.z * b.w;
            acc[3][0] += a.w * b.x; acc[3][1] += a.w * b.y; acc[3][2] += a.w * b.z; acc[3][3] += a.w * b.w;
        }
        __syncthreads();
    }
    #pragma unroll
    for (int r = 0; r < 4; r++) {
        float4 o = make_float4(acc[r][0], acc[r][1], acc[r][2], acc[r][3]);
        *(float4*)(out + (size_t)(m0 + tm * 4 + r) * N + (n0 + tn * 4)) = o;
    }
}

// dst[r*ldd + c] = sum_z slab[z*MN + r*N + c]   (deterministic)
__global__ void reduce_add(const float* __restrict__ slab, float* __restrict__ dst,
                           int MN, int Z, int N, int ldd)
{
    int i = blockIdx.x * 256 + threadIdx.x;
    if (i >= MN) return;
    float s = 0.f;
    for (int z = 0; z < Z; z++) s += slab[(size_t)z * MN + i];
    int r = i / N, c = i - r * N;
    dst[(size_t)r * ldd + c] = s;
}

// ---------------------------------------------------------------------------
// K_d = W_{d&15} * V_{d>>4} (+D for d==0) -> tf32-rounded bank g_K[d][i][o].
// ---------------------------------------------------------------------------
__global__ __launch_bounds__(256) void k_assemble(const float* __restrict__ Dm)
{
    const float* Wc = g_scratch + OFF_W;
    const float* Vc = g_scratch + OFF_V;
    const int d = blockIdx.x;
    const int d1 = d & 15, j = d >> 4;
    const float* A = Wc + (size_t)d1 * 64 * NST;
    const float* B = Vc + j * 64;

    __shared__ float As[16][68];
    __shared__ float Bs[16][68];
    const int tid = threadIdx.x;
    const int tn = tid & 15, tm = tid >> 4;
    const int la_m = (tid * 4) >> 4;
    const int la_k = (tid * 4) & 15;
    const int lb_k = (tid * 4) >> 6;
    const int lb_n = (tid * 4) & 63;
    float acc[4][4] = {};

    for (int k0 = 0; k0 < NST; k0 += 16) {
        float4 av = *(const float4*)(A + (size_t)la_m * NST + (k0 + la_k));
        As[la_k + 0][la_m] = av.x; As[la_k + 1][la_m] = av.y;
        As[la_k + 2][la_m] = av.z; As[la_k + 3][la_m] = av.w;
        float4 bv = *(const float4*)(B + (size_t)(k0 + lb_k) * VW + lb_n);
        *(float4*)&Bs[lb_k][lb_n] = bv;
        __syncthreads();
        #pragma unroll
        for (int kk = 0; kk < 16; kk++) {
            float4 a = *(const float4*)&As[kk][tm * 4];
            float4 b = *(const float4*)&Bs[kk][tn * 4];
            acc[0][0] += a.x * b.x; acc[0][1] += a.x * b.y; acc[0][2] += a.x * b.z; acc[0][3] += a.x * b.w;
            acc[1][0] += a.y * b.x; acc[1][1] += a.y * b.y; acc[1][2] += a.y * b.z; acc[1][3] += a.y * b.w;
            acc[2][0] += a.z * b.x; acc[2][1] += a.z * b.y; acc[2][2] += a.z * b.z; acc[2][3] += a.z * b.w;
            acc[3][0] += a.w * b.x; acc[3][1] += a.w * b.y; acc[3][2] += a.w * b.z; acc[3][3] += a.w * b.w;
        }
        __syncthreads();
    }
    // out: B-operand layout [i][o], row stride KSTR, tf32 rounded
    float* out = g_K + (size_t)d * TAPF;
    #pragma unroll
    for (int r = 0; r < 4; r++) {
        #pragma unroll
        for (int c = 0; c < 4; c++) {
            int o = tm * 4 + r, i = tn * 4 + c;
            float v = acc[r][c];
            if (d == 0) v += Dm[o * DIN + i];
            out[i * KSTR + o] = tf32r(v);
        }
    }
}

// ---------------------------------------------------------------------------
// tf32 mma.sync conv. 256 thr = 8 warps, each computing a 16t x 64o tile.
// K taps streamed via cp.async.bulk into a 4-stage ring.
// ---------------------------------------------------------------------------
__global__ __launch_bounds__(256, 1) void conv_tc(const float* __restrict__ x,
                                                  float* __restrict__ y)
{
    extern __shared__ char sm[];
    float* Xs = (float*)(sm + SM_X);
    const uint32_t sb = smem_u32(sm);
    const uint32_t barF = sb + SM_BAR;        // full[0..3] at +0,8,16,24
    const uint32_t barE = sb + SM_BAR + 32;   // empty[0..3]
    const int tid = threadIdx.x;
    const int wid = tid >> 5, lane = tid & 31;
    const int gid = lane >> 2, tig = lane & 3;
    const int b = blockIdx.y;
    const int t0 = blockIdx.x * TM;

    if (tid == 0) {
        #pragma unroll
        for (int s = 0; s < NSTG; s++) {
            MBAR_INIT(barF + s * 8, 1);
            MBAR_INIT(barE + s * 8, 8);
        }
    }
    __syncthreads();

    // kick off first NSTG tap fills
    if (tid == 0) {
        #pragma unroll
        for (int s = 0; s < NSTG; s++) {
            MBAR_EXPECT_TX(barF + s * 8, TAPB);
            bulk_g2s(sb + SM_K + s * TAPB, g_K + (size_t)s * TAPF, TAPB, barF + s * 8);
        }
    }

    // stage X window: row u <-> global t = t0 - 111 + u, u in [0,239)
    for (int u = tid; u < 239; u += 256) {
        int tg = t0 - (DMAX - 1) + u;
        float* dst = Xs + u * XSTR;
        if (tg >= 0) {
            const float4* src = (const float4*)(x + ((size_t)b * SEQ + tg) * DIN);
            #pragma unroll
            for (int c = 0; c < 16; c++) {
                float4 v = src[c];
                v.x = tf32r(v.x); v.y = tf32r(v.y);
                v.z = tf32r(v.z); v.w = tf32r(v.w);
                *(float4*)(dst + c * 4) = v;
            }
        } else {
            #pragma unroll
            for (int c = 0; c < 16; c++)
                *(float4*)(dst + c * 4) = make_float4(0.f, 0.f, 0.f, 0.f);
        }
    }
    __syncthreads();

    float acc[8][4];
    #pragma unroll
    for (int nf = 0; nf < 8; nf++) {
        acc[nf][0] = 0.f; acc[nf][1] = 0.f; acc[nf][2] = 0.f; acc[nf][3] = 0.f;
    }

    const float* arow = Xs + (wid * 16 + gid) * XSTR + tig;

    for (int d = 0; d < DMAX; d++) {
        const int s = d & 3;
        const uint32_t par = (d >> 2) & 1;
        MBAR_WAIT(barF + s * 8, par);

        const float* ab = arow + (DMAX - 1 - d) * XSTR;
        const float* bb = (const float*)(sm + SM_K + s * TAPB) + tig * KSTR + gid;

        #pragma unroll
        for (int kc = 0; kc < 8; kc++) {
            uint32_t a0 = __float_as_uint(ab[kc * 8]);
            uint32_t a1 = __float_as_uint(ab[kc * 8 + 8 * XSTR]);
            uint32_t a2 = __float_as_uint(ab[kc * 8 + 4]);
            uint32_t a3 = __float_as_uint(ab[kc * 8 + 8 * XSTR + 4]);
            const float* bk = bb + kc * 8 * KSTR;
            #pragma unroll
            for (int nf = 0; nf < 8; nf++) {
                uint32_t b0 = __float_as_uint(bk[nf * 8]);
                uint32_t b1 = __float_as_uint(bk[4 * KSTR + nf * 8]);
                mma_tf32(acc[nf], a0, a1, a2, a3, b0, b1);
            }
        }

        if (lane == 0) MBAR_ARRIVE(barE + s * 8);
        if (tid == 0 && d + NSTG < DMAX) {
            MBAR_WAIT(barE + s * 8, par);
            MBAR_EXPECT_TX(barF + s * 8, TAPB);
            bulk_g2s(sb + SM_K + s * TAPB, g_K + (size_t)(d + NSTG) * TAPF, TAPB,
                     barF + s * 8);
        }
    }

    // epilogue: D frag rows gid, gid+8; cols 2*tig, 2*tig+1 per 8-col nfrag
    const int r0 = t0 + wid * 16 + gid;
    #pragma unroll
    for (int nf = 0; nf < 8; nf++) {
        int col = nf * 8 + 2 * tig;
        *(float2*)(y + ((size_t)b * SEQ + r0) * DIN + col) =
            make_float2(acc[nf][0], acc[nf][1]);
        *(float2*)(y + ((size_t)b * SEQ + r0 + 8) * DIN + col) =
            make_float2(acc[nf][2], acc[nf][3]);
    }
}

// ---------------------------------------------------------------------------
extern "C" void kernel_launch(void* const* d_in, const int* in_sizes, int n_in,
                              void* d_out, int out_size)
{
    const float* x  = (const float*)d_in[0];
    const float* A  = (const float*)d_in[1];
    const float* Bm = (const float*)d_in[2];
    const float* Cm = (const float*)d_in[3];
    const float* Dm = (const float*)d_in[4];
    float* y = (float*)d_out;

    float* s = nullptr;
    cudaGetSymbolAddress((void**)&s, g_scratch);
    float* P2  = s + OFF_P2;  float* P4  = s + OFF_P4;
    float* P8  = s + OFF_P8;  float* P16 = s + OFF_P16;
    float* P32 = s + OFF_P32; float* P64 = s + OFF_P64;
    float* W   = s + OFF_W;   float* V   = s + OFF_V;
    float* SL  = s + OFF_SLAB;

    cudaFuncSetAttribute(conv_tc, cudaFuncAttributeMaxDynamicSharedMemorySize, SM_TOTAL);

    // seed W row-block 0 <- C ; V col-block 0 <- B
    cudaMemcpyAsync(W, Cm, (size_t)64 * NST * sizeof(float), cudaMemcpyDeviceToDevice);
    cudaMemcpy2DAsync(V, VW * sizeof(float), Bm, 64 * sizeof(float),
                      64 * sizeof(float), NST, cudaMemcpyDeviceToDevice);

    dim3 thr(256);
    #define RED(dst, MN, Z, N, LD) \
        reduce_add<<<((MN) + 255) / 256, 256>>>(SL, dst, MN, Z, N, LD)

    // powers A^2 .. A^64 (doubling), split-K z=4
    gemm_sk<<<dim3(8,8,4), thr>>>(A,   A,   SL, 512, 512, 128, 512, 512); RED(P2,  262144, 4, 512, 512);
    gemm_sk<<<dim3(8,8,4), thr>>>(P2,  P2,  SL, 512, 512, 128, 512, 512); RED(P4,  262144, 4, 512, 512);
    gemm_sk<<<dim3(8,8,4), thr>>>(P4,  P4,  SL, 512, 512, 128, 512, 512); RED(P8,  262144, 4, 512, 512);
    gemm_sk<<<dim3(8,8,4), thr>>>(P8,  P8,  SL, 512, 512, 128, 512, 512); RED(P16, 262144, 4, 512, 512);
    gemm_sk<<<dim3(8,8,4), thr>>>(P16, P16, SL, 512, 512, 128, 512, 512); RED(P32, 262144, 4, 512, 512);
    gemm_sk<<<dim3(8,8,4), thr>>>(P32, P32, SL, 512, 512, 128, 512, 512); RED(P64, 262144, 4, 512, 512);
    // W stack: W_d = C A^d, d = 0..15
    gemm_sk<<<dim3(8,1,8), thr>>>(W, A,  SL,  64, 512,  64, 512, 512); RED(W + (size_t)64  * 512,  32768, 8, 512, 512);
    gemm_sk<<<dim3(8,2,8), thr>>>(W, P2, SL, 128, 512,  64, 512, 512); RED(W + (size_t)128 * 512,  65536, 8, 512, 512);
    gemm_sk<<<dim3(8,4,4), thr>>>(W, P4, SL, 256, 512, 128, 512, 512); RED(W + (size_t)256 * 512, 131072, 4, 512, 512);
    gemm_sk<<<dim3(8,8,4), thr>>>(W, P8, SL, 512, 512, 128, 512, 512); RED(W + (size_t)512 * 512, 262144, 4, 512, 512);
    // V stack: V_j = A^{16j} B (col blocks of width 64 in Vcat, ld=VW)
    gemm_sk<<<dim3(1,8,8), thr>>>(P16, V, SL, 512,  64,  64, 512, VW); RED(V + 64,  32768, 8,  64, VW);
    gemm_sk<<<dim3(2,8,8), thr>>>(P32, V, SL, 512, 128,  64, 512, VW); RED(V + 128, 65536, 8, 128, VW);
    gemm_sk<<<dim3(3,8,4), thr>>>(P64, V, SL, 512, 192, 128, 512, VW); RED(V + 256, 98304, 4, 192, VW);
    #undef RED

    // tap bank (tf32-rounded, B-operand layout, D folded into tap 0)
    k_assemble<<<DMAX, thr>>>(Dm);
    // tensor-core convolution (mma.sync tf32)
    conv_tc<<<dim3(SEQ / TM, BATCH), 256, SM_TOTAL>>>(x, y);
}

// round 6
// speedup vs baseline: 5.3406x; 1.5014x over previous
#include <cuda_runtime.h>
#include <cuda_fp16.h>
#include <cstdint>

// ---------------------------------------------------------------------------
// Linear SSM as truncated causal conv: y[t] = sum_{d<112} K_d x[t-d], K_0+=D.
// Stage 1: fp32 split-K GEMM chain builds K_d = C A^d B -> fp16 tap bank.
// Stage 2: mma.sync m16n8k16 fp16 conv (fp16 u = 2^-11 == tf32, 2x rate).
//          X window in smem fp16 (stride 72 halves, conflict-free frags),
//          K taps streamed via cp.async.bulk + 4-stage mbarrier ring.
//          Toeplitz tap shift = A-frag row offset. fp32 accumulate.
// ---------------------------------------------------------------------------

#define SEQ   4096
#define BATCH 16
#define DIN   64
#define NST   512
#define DMAX  112
#define TM    128
#define VW    448

#define XSTRH 72            // X smem row stride (halves)
#define KSTRH 72            // K tap row stride (halves)
#define TAPH  4608          // halves per tap (64*72)
#define TAPB  9216          // bytes per tap
#define NSTG  4

#define SM_X    0
#define SM_K    34560       // 240*72*2
#define SM_BAR  71424       // 34560 + 4*9216
#define SM_TOTAL 71552

// fp32 scratch for stage 1
#define OFF_P2   0
#define OFF_P4   262144
#define OFF_P8   524288
#define OFF_P16  786432
#define OFF_P32  1048576
#define OFF_P64  1310720
#define OFF_W    1572864
#define OFF_V    2097152
#define OFF_SLAB 2326528
#define SCRATCH_FLOATS 3375104
__device__ float g_scratch[SCRATCH_FLOATS];

// fp16 tap bank: g_K[d*TAPH + o*KSTRH + i]   ([n][k] layout for B operand)
__device__ __half g_K[DMAX * TAPH];

// ---------------- PTX helpers ----------------
__device__ __forceinline__ uint32_t smem_u32(const void* p) {
    uint32_t a;
    asm("{ .reg .u64 t; cvta.to.shared.u64 t, %1; cvt.u32.u64 %0, t; }"
        : "=r"(a) : "l"(p));
    return a;
}
#define MBAR_INIT(addr, cnt) \
    asm volatile("mbarrier.init.shared.b64 [%0], %1;" :: "r"(addr), "r"(cnt) : "memory")
#define MBAR_EXPECT_TX(addr, bytes) \
    asm volatile("mbarrier.arrive.expect_tx.shared.b64 _, [%0], %1;" :: "r"(addr), "r"(bytes) : "memory")
#define MBAR_ARRIVE(addr) \
    asm volatile("mbarrier.arrive.release.cta.shared.b64 _, [%0];" :: "r"(addr) : "memory")
#define MBAR_WAIT(addr, par) do { \
    uint32_t _m = (addr), _p = (par), _d; \
    asm volatile("{\n\t.reg .pred p;\n\t" \
        "mbarrier.try_wait.parity.acquire.cta.shared::cta.b64 p, [%1], %2;\n\t" \
        "selp.b32 %0, 1, 0, p;\n\t}" : "=r"(_d) : "r"(_m), "r"(_p) : "memory"); \
    if (!_d) { \
        asm volatile("{\n\t.reg .pred P1;\n\t" \
            "WL_%=:\n\t" \
            "mbarrier.try_wait.parity.acquire.cta.shared::cta.b64 P1, [%0], %1, 0x989680;\n\t" \
            "@P1 bra.uni WD_%=;\n\t" \
            "bra.uni WL_%=;\n\t" \
            "WD_%=:\n\t}" :: "r"(_m), "r"(_p) : "memory"); \
    } \
} while (0)
__device__ __forceinline__ void bulk_g2s(uint32_t dst, const void* src,
                                         uint32_t bytes, uint32_t mbar) {
    asm volatile("cp.async.bulk.shared::cta.global.mbarrier::complete_tx::bytes "
        "[%0], [%1], %2, [%3];" :: "r"(dst), "l"(src), "r"(bytes), "r"(mbar) : "memory");
}
__device__ __forceinline__ void mma_f16(float* c, uint32_t a0, uint32_t a1,
                                        uint32_t a2, uint32_t a3,
                                        uint32_t b0, uint32_t b1) {
    asm volatile("mma.sync.aligned.m16n8k16.row.col.f32.f16.f16.f32 "
        "{%0,%1,%2,%3}, {%4,%5,%6,%7}, {%8,%9}, {%0,%1,%2,%3};"
        : "+f"(c[0]), "+f"(c[1]), "+f"(c[2]), "+f"(c[3])
        : "r"(a0), "r"(a1), "r"(a2), "r"(a3), "r"(b0), "r"(b1));
}
__device__ __forceinline__ uint32_t pack_h2(float a, float b) {
    __half2 t;
    t.x = __float2half_rn(a);
    t.y = __float2half_rn(b);
    return *(uint32_t*)&t;
}

// ---------------------------------------------------------------------------
// fp32 split-K GEMM: slab z computes A[:,zKc:(z+1)Kc] * B[zKc:(z+1)Kc,:]
// into out + z*M*N (dense). Tile 64x64, 256 thr, 4x4 micro.
// ---------------------------------------------------------------------------
__global__ __launch_bounds__(256) void gemm_sk(
    const float* __restrict__ A, const float* __restrict__ B, float* __restrict__ out,
    int M, int N, int Kc, int lda, int ldb)
{
    A += (size_t)blockIdx.z * Kc;
    B += (size_t)blockIdx.z * Kc * ldb;
    out += (size_t)blockIdx.z * M * N;
    __shared__ float As[16][68];
    __shared__ float Bs[16][68];
    const int tid = threadIdx.x;
    const int m0 = blockIdx.y * 64, n0 = blockIdx.x * 64;
    const int tn = tid & 15, tm = tid >> 4;
    const int la_m = (tid * 4) >> 4;
    const int la_k = (tid * 4) & 15;
    const int lb_k = (tid * 4) >> 6;
    const int lb_n = (tid * 4) & 63;
    float acc[4][4] = {};

    for (int k0 = 0; k0 < Kc; k0 += 16) {
        float4 av = *(const float4*)(A + (size_t)(m0 + la_m) * lda + (k0 + la_k));
        As[la_k + 0][la_m] = av.x; As[la_k + 1][la_m] = av.y;
        As[la_k + 2][la_m] = av.z; As[la_k + 3][la_m] = av.w;
        float4 bv = *(const float4*)(B + (size_t)(k0 + lb_k) * ldb + (n0 + lb_n));
        *(float4*)&Bs[lb_k][lb_n] = bv;
        __syncthreads();
        #pragma unroll
        for (int kk = 0; kk < 16; kk++) {
            float4 a = *(const float4*)&As[kk][tm * 4];
            float4 b = *(const float4*)&Bs[kk][tn * 4];
            acc[0][0] += a.x * b.x; acc[0][1] += a.x * b.y; acc[0][2] += a.x * b.z; acc[0][3] += a.x * b.w;
            acc[1][0] += a.y * b.x; acc[1][1] += a.y * b.y; acc[1][2] += a.y * b.z; acc[1][3] += a.y * b.w;
            acc[2][0] += a.z * b.x; acc[2][1] += a.z * b.y; acc[2][2] += a.z * b.z; acc[2][3] += a.z * b.w;
            acc[3][0] += a.w * b.x; acc[3][1] += a.w * b.y; acc[3][2] += a.w * b.z; acc[3][3] += a.w * b.w;
        }
        __syncthreads();
    }
    #pragma unroll
    for (int r = 0; r < 4; r++) {
        float4 o = make_float4(acc[r][0], acc[r][1], acc[r][2], acc[r][3]);
        *(float4*)(out + (size_t)(m0 + tm * 4 + r) * N + (n0 + tn * 4)) = o;
    }
}

// dst[r*ldd + c] = sum_z slab[z*MN + r*N + c]   (deterministic, float4)
__global__ void reduce_add(const float* __restrict__ slab, float* __restrict__ dst,
                           int MN, int Z, int N, int ldd)
{
    int i4 = blockIdx.x * 256 + threadIdx.x;   // float4 index
    if (i4 * 4 >= MN) return;
    float4 s = make_float4(0.f, 0.f, 0.f, 0.f);
    for (int z = 0; z < Z; z++) {
        float4 v = *(const float4*)(slab + (size_t)z * MN + i4 * 4);
        s.x += v.x; s.y += v.y; s.z += v.z; s.w += v.w;
    }
    int i = i4 * 4;
    int r = i / N, c = i - r * N;
    *(float4*)(dst + (size_t)r * ldd + c) = s;
}

// ---------------------------------------------------------------------------
// K_d = W_{d&15} * V_{d>>4} (+D for d==0) -> fp16 bank g_K[d][o][i].
// ---------------------------------------------------------------------------
__global__ __launch_bounds__(256) void k_assemble(const float* __restrict__ Dm)
{
    const float* Wc = g_scratch + OFF_W;
    const float* Vc = g_scratch + OFF_V;
    const int d = blockIdx.x;
    const int d1 = d & 15, j = d >> 4;
    const float* A = Wc + (size_t)d1 * 64 * NST;
    const float* B = Vc + j * 64;

    __shared__ float As[16][68];
    __shared__ float Bs[16][68];
    const int tid = threadIdx.x;
    const int tn = tid & 15, tm = tid >> 4;
    const int la_m = (tid * 4) >> 4;
    const int la_k = (tid * 4) & 15;
    const int lb_k = (tid * 4) >> 6;
    const int lb_n = (tid * 4) & 63;
    float acc[4][4] = {};

    for (int k0 = 0; k0 < NST; k0 += 16) {
        float4 av = *(const float4*)(A + (size_t)la_m * NST + (k0 + la_k));
        As[la_k + 0][la_m] = av.x; As[la_k + 1][la_m] = av.y;
        As[la_k + 2][la_m] = av.z; As[la_k + 3][la_m] = av.w;
        float4 bv = *(const float4*)(B + (size_t)(k0 + lb_k) * VW + lb_n);
        *(float4*)&Bs[lb_k][lb_n] = bv;
        __syncthreads();
        #pragma unroll
        for (int kk = 0; kk < 16; kk++) {
            float4 a = *(const float4*)&As[kk][tm * 4];
            float4 b = *(const float4*)&Bs[kk][tn * 4];
            acc[0][0] += a.x * b.x; acc[0][1] += a.x * b.y; acc[0][2] += a.x * b.z; acc[0][3] += a.x * b.w;
            acc[1][0] += a.y * b.x; acc[1][1] += a.y * b.y; acc[1][2] += a.y * b.z; acc[1][3] += a.y * b.w;
            acc[2][0] += a.z * b.x; acc[2][1] += a.z * b.y; acc[2][2] += a.z * b.z; acc[2][3] += a.z * b.w;
            acc[3][0] += a.w * b.x; acc[3][1] += a.w * b.y; acc[3][2] += a.w * b.z; acc[3][3] += a.w * b.w;
        }
        __syncthreads();
    }
    // B-operand layout [o][i] (n-major, k contiguous), fp16
    __half* out = g_K + (size_t)d * TAPH;
    #pragma unroll
    for (int r = 0; r < 4; r++) {
        #pragma unroll
        for (int c = 0; c < 4; c++) {
            int o = tm * 4 + r, i = tn * 4 + c;
            float v = acc[r][c];
            if (d == 0) v += Dm[o * DIN + i];
            out[o * KSTRH + i] = __float2half_rn(v);
        }
    }
}

// ---------------------------------------------------------------------------
// fp16 mma.sync conv. 256 thr = 8 warps, each computing a 16t x 64o tile.
// K taps streamed via cp.async.bulk into a 4-stage ring.
// ---------------------------------------------------------------------------
__global__ __launch_bounds__(256, 2) void conv_tc(const float* __restrict__ x,
                                                  float* __restrict__ y)
{
    extern __shared__ char sm[];
    __half* Xs = (__half*)(sm + SM_X);
    const uint32_t sb = smem_u32(sm);
    const uint32_t barF = sb + SM_BAR;        // full[0..3] at +0,8,16,24
    const uint32_t barE = sb + SM_BAR + 32;   // empty[0..3]
    const int tid = threadIdx.x;
    const int wid = tid >> 5, lane = tid & 31;
    const int gid = lane >> 2, tig = lane & 3;
    const int b = blockIdx.y;
    const int t0 = blockIdx.x * TM;

    if (tid == 0) {
        #pragma unroll
        for (int s = 0; s < NSTG; s++) {
            MBAR_INIT(barF + s * 8, 1);
            MBAR_INIT(barE + s * 8, 8);
        }
    }
    __syncthreads();

    // kick off first NSTG tap fills
    if (tid == 0) {
        #pragma unroll
        for (int s = 0; s < NSTG; s++) {
            MBAR_EXPECT_TX(barF + s * 8, TAPB);
            bulk_g2s(sb + SM_K + s * TAPB, g_K + (size_t)s * TAPH, TAPB, barF + s * 8);
        }
    }

    // stage X window fp16: row u <-> global t = t0 - 111 + u, u in [0,239)
    for (int u = tid; u < 239; u += 256) {
        int tg = t0 - (DMAX - 1) + u;
        uint32_t* dst = (uint32_t*)(Xs + u * XSTRH);
        if (tg >= 0) {
            const float4* src = (const float4*)(x + ((size_t)b * SEQ + tg) * DIN);
            #pragma unroll
            for (int c = 0; c < 16; c += 2) {
                float4 v0 = src[c], v1 = src[c + 1];
                uint4 h;
                h.x = pack_h2(v0.x, v0.y); h.y = pack_h2(v0.z, v0.w);
                h.z = pack_h2(v1.x, v1.y); h.w = pack_h2(v1.z, v1.w);
                *(uint4*)(dst + c * 2) = h;
            }
        } else {
            #pragma unroll
            for (int c = 0; c < 8; c++)
                *(uint4*)(dst + c * 4) = make_uint4(0, 0, 0, 0);
        }
    }
    __syncthreads();

    float acc[8][4];
    #pragma unroll
    for (int nf = 0; nf < 8; nf++) {
        acc[nf][0] = 0.f; acc[nf][1] = 0.f; acc[nf][2] = 0.f; acc[nf][3] = 0.f;
    }

    const __half* arow = Xs + (wid * 16 + gid) * XSTRH + tig * 2;

    for (int d = 0; d < DMAX; d++) {
        const int s = d & 3;
        const uint32_t par = (d >> 2) & 1;
        MBAR_WAIT(barF + s * 8, par);

        const __half* ab = arow + (DMAX - 1 - d) * XSTRH;
        const __half* bb = (const __half*)(sm + SM_K + s * TAPB) + gid * KSTRH + tig * 2;

        #pragma unroll
        for (int kc = 0; kc < 4; kc++) {
            uint32_t a0 = *(const uint32_t*)(ab + kc * 16);
            uint32_t a1 = *(const uint32_t*)(ab + kc * 16 + 8 * XSTRH);
            uint32_t a2 = *(const uint32_t*)(ab + kc * 16 + 8);
            uint32_t a3 = *(const uint32_t*)(ab + kc * 16 + 8 * XSTRH + 8);
            const __half* bk = bb + kc * 16;
            #pragma unroll
            for (int nf = 0; nf < 8; nf++) {
                uint32_t b0 = *(const uint32_t*)(bk + nf * 8 * KSTRH);
                uint32_t b1 = *(const uint32_t*)(bk + nf * 8 * KSTRH + 8);
                mma_f16(acc[nf], a0, a1, a2, a3, b0, b1);
            }
        }

        if (lane == 0) MBAR_ARRIVE(barE + s * 8);
        if (tid == 0 && d + NSTG < DMAX) {
            MBAR_WAIT(barE + s * 8, par);
            MBAR_EXPECT_TX(barF + s * 8, TAPB);
            bulk_g2s(sb + SM_K + s * TAPB, g_K + (size_t)(d + NSTG) * TAPH, TAPB,
                     barF + s * 8);
        }
    }

    // epilogue: D frag rows gid, gid+8; cols 2*tig, 2*tig+1 per 8-col nfrag
    const int r0 = t0 + wid * 16 + gid;
    #pragma unroll
    for (int nf = 0; nf < 8; nf++) {
        int col = nf * 8 + 2 * tig;
        *(float2*)(y + ((size_t)b * SEQ + r0) * DIN + col) =
            make_float2(acc[nf][0], acc[nf][1]);
        *(float2*)(y + ((size_t)b * SEQ + r0 + 8) * DIN + col) =
            make_float2(acc[nf][2], acc[nf][3]);
    }
}

// ---------------------------------------------------------------------------
extern "C" void kernel_launch(void* const* d_in, const int* in_sizes, int n_in,
                              void* d_out, int out_size)
{
    const float* x  = (const float*)d_in[0];
    const float* A  = (const float*)d_in[1];
    const float* Bm = (const float*)d_in[2];
    const float* Cm = (const float*)d_in[3];
    const float* Dm = (const float*)d_in[4];
    float* y = (float*)d_out;

    float* s = nullptr;
    cudaGetSymbolAddress((void**)&s, g_scratch);
    float* P2  = s + OFF_P2;  float* P4  = s + OFF_P4;
    float* P8  = s + OFF_P8;  float* P16 = s + OFF_P16;
    float* P32 = s + OFF_P32; float* P64 = s + OFF_P64;
    float* W   = s + OFF_W;   float* V   = s + OFF_V;
    float* SL  = s + OFF_SLAB;

    cudaFuncSetAttribute(conv_tc, cudaFuncAttributeMaxDynamicSharedMemorySize, SM_TOTAL);

    // seed W row-block 0 <- C ; V col-block 0 <- B
    cudaMemcpyAsync(W, Cm, (size_t)64 * NST * sizeof(float), cudaMemcpyDeviceToDevice);
    cudaMemcpy2DAsync(V, VW * sizeof(float), Bm, 64 * sizeof(float),
                      64 * sizeof(float), NST, cudaMemcpyDeviceToDevice);

    dim3 thr(256);
    #define RED(dst, MN, Z, N, LD) \
        reduce_add<<<((MN) / 4 + 255) / 256, 256>>>(SL, dst, MN, Z, N, LD)

    // powers A^2 .. A^64 (doubling), split-K z=4
    gemm_sk<<<dim3(8,8,4), thr>>>(A,   A,   SL, 512, 512, 128, 512, 512); RED(P2,  262144, 4, 512, 512);
    gemm_sk<<<dim3(8,8,4), thr>>>(P2,  P2,  SL, 512, 512, 128, 512, 512); RED(P4,  262144, 4, 512, 512);
    gemm_sk<<<dim3(8,8,4), thr>>>(P4,  P4,  SL, 512, 512, 128, 512, 512); RED(P8,  262144, 4, 512, 512);
    gemm_sk<<<dim3(8,8,4), thr>>>(P8,  P8,  SL, 512, 512, 128, 512, 512); RED(P16, 262144, 4, 512, 512);
    gemm_sk<<<dim3(8,8,4), thr>>>(P16, P16, SL, 512, 512, 128, 512, 512); RED(P32, 262144, 4, 512, 512);
    gemm_sk<<<dim3(8,8,4), thr>>>(P32, P32, SL, 512, 512, 128, 512, 512); RED(P64, 262144, 4, 512, 512);
    // W stack: W_d = C A^d, d = 0..15
    gemm_sk<<<dim3(8,1,8), thr>>>(W, A,  SL,  64, 512,  64, 512, 512); RED(W + (size_t)64  * 512,  32768, 8, 512, 512);
    gemm_sk<<<dim3(8,2,8), thr>>>(W, P2, SL, 128, 512,  64, 512, 512); RED(W + (size_t)128 * 512,  65536, 8, 512, 512);
    gemm_sk<<<dim3(8,4,4), thr>>>(W, P4, SL, 256, 512, 128, 512, 512); RED(W + (size_t)256 * 512, 131072, 4, 512, 512);
    gemm_sk<<<dim3(8,8,4), thr>>>(W, P8, SL, 512, 512, 128, 512, 512); RED(W + (size_t)512 * 512, 262144, 4, 512, 512);
    // V stack: V_j = A^{16j} B (col blocks of width 64 in Vcat, ld=VW)
    gemm_sk<<<dim3(1,8,8), thr>>>(P16, V, SL, 512,  64,  64, 512, VW); RED(V + 64,  32768, 8,  64, VW);
    gemm_sk<<<dim3(2,8,8), thr>>>(P32, V, SL, 512, 128,  64, 512, VW); RED(V + 128, 65536, 8, 128, VW);
    gemm_sk<<<dim3(3,8,4), thr>>>(P64, V, SL, 512, 192, 128, 512, VW); RED(V + 256, 98304, 4, 192, VW);
    #undef RED

    // tap bank (fp16, B-operand layout, D folded into tap 0)
    k_assemble<<<DMAX, thr>>>(Dm);
    // tensor-core convolution (mma.sync fp16, fp32 accumulate)
    conv_tc<<<dim3(SEQ / TM, BATCH), 256, SM_TOTAL>>>(x, y);
}

// round 7
// speedup vs baseline: 5.6617x; 1.0601x over previous
#include <cuda_runtime.h>
#include <cuda_fp16.h>
#include <cstdint>

// ---------------------------------------------------------------------------
// Linear SSM as truncated causal conv: y[t] = sum_{d<112} K_d x[t-d], K_0+=D.
// Stage 1: fp32 split-K (z=8) GEMM chain builds K_d = C A^d B -> fp16 bank.
// Stage 2: mma.sync m16n8k16 fp16 conv, ldmatrix.x4 operand loads (20 LDSM +
//          32 MMA per warp-tap), K taps via cp.async.bulk 4-stage ring.
//          Toeplitz tap shift = A-frag base row offset. fp32 accumulate.
// ---------------------------------------------------------------------------

#define SEQ   4096
#define BATCH 16
#define DIN   64
#define NST   512
#define DMAX  112
#define TM    128
#define VW    448

#define XSTRH 72            // X smem row stride (halves) -> 144 B
#define KSTRH 72
#define TAPH  4608          // halves per tap (64*72)
#define TAPB  9216          // bytes per tap
#define NSTG  4

#define SM_X    0
#define SM_K    34560       // 240*72*2
#define SM_BAR  71424       // 34560 + 4*9216
#define SM_TOTAL 71552

// fp32 scratch for stage 1
#define OFF_P2   0
#define OFF_P4   262144
#define OFF_P8   524288
#define OFF_P16  786432
#define OFF_P32  1048576
#define OFF_P64  1310720
#define OFF_W    1572864
#define OFF_V    2097152
#define OFF_SLAB 2326528
#define SCRATCH_FLOATS 4423680     // slab holds up to 8*512*512
__device__ float g_scratch[SCRATCH_FLOATS];

// fp16 tap bank: g_K[d*TAPH + o*KSTRH + i]   ([n][k] layout for B operand)
__device__ __half g_K[DMAX * TAPH];

// ---------------- PTX helpers ----------------
__device__ __forceinline__ uint32_t smem_u32(const void* p) {
    uint32_t a;
    asm("{ .reg .u64 t; cvta.to.shared.u64 t, %1; cvt.u32.u64 %0, t; }"
        : "=r"(a) : "l"(p));
    return a;
}
#define MBAR_INIT(addr, cnt) \
    asm volatile("mbarrier.init.shared.b64 [%0], %1;" :: "r"(addr), "r"(cnt) : "memory")
#define MBAR_EXPECT_TX(addr, bytes) \
    asm volatile("mbarrier.arrive.expect_tx.shared.b64 _, [%0], %1;" :: "r"(addr), "r"(bytes) : "memory")
#define MBAR_ARRIVE(addr) \
    asm volatile("mbarrier.arrive.release.cta.shared.b64 _, [%0];" :: "r"(addr) : "memory")
#define MBAR_WAIT(addr, par) do { \
    uint32_t _m = (addr), _p = (par), _d; \
    asm volatile("{\n\t.reg .pred p;\n\t" \
        "mbarrier.try_wait.parity.acquire.cta.shared::cta.b64 p, [%1], %2;\n\t" \
        "selp.b32 %0, 1, 0, p;\n\t}" : "=r"(_d) : "r"(_m), "r"(_p) : "memory"); \
    if (!_d) { \
        asm volatile("{\n\t.reg .pred P1;\n\t" \
            "WL_%=:\n\t" \
            "mbarrier.try_wait.parity.acquire.cta.shared::cta.b64 P1, [%0], %1, 0x989680;\n\t" \
            "@P1 bra.uni WD_%=;\n\t" \
            "bra.uni WL_%=;\n\t" \
            "WD_%=:\n\t}" :: "r"(_m), "r"(_p) : "memory"); \
    } \
} while (0)
__device__ __forceinline__ void bulk_g2s(uint32_t dst, const void* src,
                                         uint32_t bytes, uint32_t mbar) {
    asm volatile("cp.async.bulk.shared::cta.global.mbarrier::complete_tx::bytes "
        "[%0], [%1], %2, [%3];" :: "r"(dst), "l"(src), "r"(bytes), "r"(mbar) : "memory");
}
__device__ __forceinline__ void mma_f16(float* c, uint32_t a0, uint32_t a1,
                                        uint32_t a2, uint32_t a3,
                                        uint32_t b0, uint32_t b1) {
    asm volatile("mma.sync.aligned.m16n8k16.row.col.f32.f16.f16.f32 "
        "{%0,%1,%2,%3}, {%4,%5,%6,%7}, {%8,%9}, {%0,%1,%2,%3};"
        : "+f"(c[0]), "+f"(c[1]), "+f"(c[2]), "+f"(c[3])
        : "r"(a0), "r"(a1), "r"(a2), "r"(a3), "r"(b0), "r"(b1));
}
#define LDSM4(r0, r1, r2, r3, addr) \
    asm volatile("ldmatrix.sync.aligned.m8n8.x4.shared.b16 {%0,%1,%2,%3}, [%4];" \
        : "=r"(r0), "=r"(r1), "=r"(r2), "=r"(r3) : "r"(addr))
__device__ __forceinline__ uint32_t pack_h2(float a, float b) {
    __half2 t;
    t.x = __float2half_rn(a);
    t.y = __float2half_rn(b);
    return *(uint32_t*)&t;
}

// ---------------------------------------------------------------------------
// fp32 split-K GEMM: slab z computes A[:,zKc:(z+1)Kc] * B[zKc:(z+1)Kc,:]
// into out + z*M*N (dense). Tile 64x64, 256 thr, 4x4 micro.
// ---------------------------------------------------------------------------
__global__ __launch_bounds__(256) void gemm_sk(
    const float* __restrict__ A, const float* __restrict__ B, float* __restrict__ out,
    int M, int N, int Kc, int lda, int ldb)
{
    A += (size_t)blockIdx.z * Kc;
    B += (size_t)blockIdx.z * Kc * ldb;
    out += (size_t)blockIdx.z * M * N;
    __shared__ float As[16][68];
    __shared__ float Bs[16][68];
    const int tid = threadIdx.x;
    const int m0 = blockIdx.y * 64, n0 = blockIdx.x * 64;
    const int tn = tid & 15, tm = tid >> 4;
    const int la_m = (tid * 4) >> 4;
    const int la_k = (tid * 4) & 15;
    const int lb_k = (tid * 4) >> 6;
    const int lb_n = (tid * 4) & 63;
    float acc[4][4] = {};

    for (int k0 = 0; k0 < Kc; k0 += 16) {
        float4 av = *(const float4*)(A + (size_t)(m0 + la_m) * lda + (k0 + la_k));
        As[la_k + 0][la_m] = av.x; As[la_k + 1][la_m] = av.y;
        As[la_k + 2][la_m] = av.z; As[la_k + 3][la_m] = av.w;
        float4 bv = *(const float4*)(B + (size_t)(k0 + lb_k) * ldb + (n0 + lb_n));
        *(float4*)&Bs[lb_k][lb_n] = bv;
        __syncthreads();
        #pragma unroll
        for (int kk = 0; kk < 16; kk++) {
            float4 a = *(const float4*)&As[kk][tm * 4];
            float4 b = *(const float4*)&Bs[kk][tn * 4];
            acc[0][0] += a.x * b.x; acc[0][1] += a.x * b.y; acc[0][2] += a.x * b.z; acc[0][3] += a.x * b.w;
            acc[1][0] += a.y * b.x; acc[1][1] += a.y * b.y; acc[1][2] += a.y * b.z; acc[1][3] += a.y * b.w;
            acc[2][0] += a.z * b.x; acc[2][1] += a.z * b.y; acc[2][2] += a.z * b.z; acc[2][3] += a.z * b.w;
            acc[3][0] += a.w * b.x; acc[3][1] += a.w * b.y; acc[3][2] += a.w * b.z; acc[3][3] += a.w * b.w;
        }
        __syncthreads();
    }
    #pragma unroll
    for (int r = 0; r < 4; r++) {
        float4 o = make_float4(acc[r][0], acc[r][1], acc[r][2], acc[r][3]);
        *(float4*)(out + (size_t)(m0 + tm * 4 + r) * N + (n0 + tn * 4)) = o;
    }
}

// dst[r*ldd + c] = sum_z slab[z*MN + r*N + c]   (deterministic, float4)
__global__ void reduce_add(const float* __restrict__ slab, float* __restrict__ dst,
                           int MN, int Z, int N, int ldd)
{
    int i4 = blockIdx.x * 256 + threadIdx.x;   // float4 index
    if (i4 * 4 >= MN) return;
    float4 s = make_float4(0.f, 0.f, 0.f, 0.f);
    for (int z = 0; z < Z; z++) {
        float4 v = *(const float4*)(slab + (size_t)z * MN + i4 * 4);
        s.x += v.x; s.y += v.y; s.z += v.z; s.w += v.w;
    }
    int i = i4 * 4;
    int r = i / N, c = i - r * N;
    *(float4*)(dst + (size_t)r * ldd + c) = s;
}

// ---------------------------------------------------------------------------
// K_d = W_{d&15} * V_{d>>4} (+D for d==0) -> fp16 bank g_K[d][o][i].
// ---------------------------------------------------------------------------
__global__ __launch_bounds__(256) void k_assemble(const float* __restrict__ Dm)
{
    const float* Wc = g_scratch + OFF_W;
    const float* Vc = g_scratch + OFF_V;
    const int d = blockIdx.x;
    const int d1 = d & 15, j = d >> 4;
    const float* A = Wc + (size_t)d1 * 64 * NST;
    const float* B = Vc + j * 64;

    __shared__ float As[16][68];
    __shared__ float Bs[16][68];
    const int tid = threadIdx.x;
    const int tn = tid & 15, tm = tid >> 4;
    const int la_m = (tid * 4) >> 4;
    const int la_k = (tid * 4) & 15;
    const int lb_k = (tid * 4) >> 6;
    const int lb_n = (tid * 4) & 63;
    float acc[4][4] = {};

    for (int k0 = 0; k0 < NST; k0 += 16) {
        float4 av = *(const float4*)(A + (size_t)la_m * NST + (k0 + la_k));
        As[la_k + 0][la_m] = av.x; As[la_k + 1][la_m] = av.y;
        As[la_k + 2][la_m] = av.z; As[la_k + 3][la_m] = av.w;
        float4 bv = *(const float4*)(B + (size_t)(k0 + lb_k) * VW + lb_n);
        *(float4*)&Bs[lb_k][lb_n] = bv;
        __syncthreads();
        #pragma unroll
        for (int kk = 0; kk < 16; kk++) {
            float4 a = *(const float4*)&As[kk][tm * 4];
            float4 b = *(const float4*)&Bs[kk][tn * 4];
            acc[0][0] += a.x * b.x; acc[0][1] += a.x * b.y; acc[0][2] += a.x * b.z; acc[0][3] += a.x * b.w;
            acc[1][0] += a.y * b.x; acc[1][1] += a.y * b.y; acc[1][2] += a.y * b.z; acc[1][3] += a.y * b.w;
            acc[2][0] += a.z * b.x; acc[2][1] += a.z * b.y; acc[2][2] += a.z * b.z; acc[2][3] += a.z * b.w;
            acc[3][0] += a.w * b.x; acc[3][1] += a.w * b.y; acc[3][2] += a.w * b.z; acc[3][3] += a.w * b.w;
        }
        __syncthreads();
    }
    // B-operand layout [o][i] (n-major, k contiguous), fp16
    __half* out = g_K + (size_t)d * TAPH;
    #pragma unroll
    for (int r = 0; r < 4; r++) {
        #pragma unroll
        for (int c = 0; c < 4; c++) {
            int o = tm * 4 + r, i = tn * 4 + c;
            float v = acc[r][c];
            if (d == 0) v += Dm[o * DIN + i];
            out[o * KSTRH + i] = __float2half_rn(v);
        }
    }
}

// ---------------------------------------------------------------------------
// fp16 mma.sync conv with ldmatrix.x4 operand loads.
// 256 thr = 8 warps, each computing a 16t x 64o tile.
// ---------------------------------------------------------------------------
__global__ __launch_bounds__(256, 2) void conv_tc(const float* __restrict__ x,
                                                  float* __restrict__ y)
{
    extern __shared__ char sm[];
    __half* Xs = (__half*)(sm + SM_X);
    const uint32_t sb = smem_u32(sm);
    const uint32_t barF = sb + SM_BAR;        // full[0..3] at +0,8,16,24
    const uint32_t barE = sb + SM_BAR + 32;   // empty[0..3]
    const int tid = threadIdx.x;
    const int wid = tid >> 5, lane = tid & 31;
    const int gid = lane >> 2, tig = lane & 3;
    const int b = blockIdx.y;
    const int t0 = blockIdx.x * TM;

    if (tid == 0) {
        #pragma unroll
        for (int s = 0; s < NSTG; s++) {
            MBAR_INIT(barF + s * 8, 1);
            MBAR_INIT(barE + s * 8, 8);
        }
    }
    __syncthreads();

    // kick off first NSTG tap fills
    if (tid == 0) {
        #pragma unroll
        for (int s = 0; s < NSTG; s++) {
            MBAR_EXPECT_TX(barF + s * 8, TAPB);
            bulk_g2s(sb + SM_K + s * TAPB, g_K + (size_t)s * TAPH, TAPB, barF + s * 8);
        }
    }

    // stage X window fp16: row u <-> global t = t0 - 111 + u, u in [0,239)
    for (int u = tid; u < 239; u += 256) {
        int tg = t0 - (DMAX - 1) + u;
        uint32_t* dst = (uint32_t*)(Xs + u * XSTRH);
        if (tg >= 0) {
            const float4* src = (const float4*)(x + ((size_t)b * SEQ + tg) * DIN);
            #pragma unroll
            for (int c = 0; c < 16; c += 2) {
                float4 v0 = src[c], v1 = src[c + 1];
                uint4 h;
                h.x = pack_h2(v0.x, v0.y); h.y = pack_h2(v0.z, v0.w);
                h.z = pack_h2(v1.x, v1.y); h.w = pack_h2(v1.z, v1.w);
                *(uint4*)(dst + c * 2) = h;
            }
        } else {
            #pragma unroll
            for (int c = 0; c < 8; c++)
                *(uint4*)(dst + c * 4) = make_uint4(0, 0, 0, 0);
        }
    }
    __syncthreads();

    float acc[8][4];
    #pragma unroll
    for (int nf = 0; nf < 8; nf++) {
        acc[nf][0] = 0.f; acc[nf][1] = 0.f; acc[nf][2] = 0.f; acc[nf][3] = 0.f;
    }

    // ldmatrix per-lane address invariants (byte offsets; row stride 144B)
    const uint32_t invA = (uint32_t)(wid * 16 + (lane & 15)) * 144u
                        + (uint32_t)(lane >> 4) * 16u;
    const uint32_t invB = (uint32_t)((lane & 7) + ((lane >> 4) << 3)) * 144u
                        + (uint32_t)((lane >> 3) & 1) * 16u;

    for (int d = 0; d < DMAX; d++) {
        const int s = d & 3;
        const uint32_t par = (d >> 2) & 1;
        MBAR_WAIT(barF + s * 8, par);

        const uint32_t aBase = sb + SM_X + invA + (uint32_t)(DMAX - 1 - d) * 144u;
        const uint32_t bBase = sb + SM_K + (uint32_t)s * TAPB + invB;

        #pragma unroll
        for (int kc = 0; kc < 4; kc++) {
            uint32_t a0, a1, a2, a3;
            LDSM4(a0, a1, a2, a3, aBase + kc * 32);
            #pragma unroll
            for (int nfp = 0; nfp < 4; nfp++) {
                uint32_t b0, b1, b2, b3;
                LDSM4(b0, b1, b2, b3, bBase + nfp * 2304 + kc * 32);
                mma_f16(acc[2 * nfp],     a0, a1, a2, a3, b0, b1);
                mma_f16(acc[2 * nfp + 1], a0, a1, a2, a3, b2, b3);
            }
        }

        if (lane == 0) MBAR_ARRIVE(barE + s * 8);
        if (tid == 0 && d + NSTG < DMAX) {
            MBAR_WAIT(barE + s * 8, par);
            MBAR_EXPECT_TX(barF + s * 8, TAPB);
            bulk_g2s(sb + SM_K + s * TAPB, g_K + (size_t)(d + NSTG) * TAPH, TAPB,
                     barF + s * 8);
        }
    }

    // epilogue: D frag rows gid, gid+8; cols 2*tig, 2*tig+1 per 8-col nfrag
    const int r0 = t0 + wid * 16 + gid;
    #pragma unroll
    for (int nf = 0; nf < 8; nf++) {
        int col = nf * 8 + 2 * tig;
        *(float2*)(y + ((size_t)b * SEQ + r0) * DIN + col) =
            make_float2(acc[nf][0], acc[nf][1]);
        *(float2*)(y + ((size_t)b * SEQ + r0 + 8) * DIN + col) =
            make_float2(acc[nf][2], acc[nf][3]);
    }
}

// ---------------------------------------------------------------------------
extern "C" void kernel_launch(void* const* d_in, const int* in_sizes, int n_in,
                              void* d_out, int out_size)
{
    const float* x  = (const float*)d_in[0];
    const float* A  = (const float*)d_in[1];
    const float* Bm = (const float*)d_in[2];
    const float* Cm = (const float*)d_in[3];
    const float* Dm = (const float*)d_in[4];
    float* y = (float*)d_out;

    float* s = nullptr;
    cudaGetSymbolAddress((void**)&s, g_scratch);
    float* P2  = s + OFF_P2;  float* P4  = s + OFF_P4;
    float* P8  = s + OFF_P8;  float* P16 = s + OFF_P16;
    float* P32 = s + OFF_P32; float* P64 = s + OFF_P64;
    float* W   = s + OFF_W;   float* V   = s + OFF_V;
    float* SL  = s + OFF_SLAB;

    cudaFuncSetAttribute(conv_tc, cudaFuncAttributeMaxDynamicSharedMemorySize, SM_TOTAL);

    // seed W row-block 0 <- C ; V col-block 0 <- B
    cudaMemcpyAsync(W, Cm, (size_t)64 * NST * sizeof(float), cudaMemcpyDeviceToDevice);
    cudaMemcpy2DAsync(V, VW * sizeof(float), Bm, 64 * sizeof(float),
                      64 * sizeof(float), NST, cudaMemcpyDeviceToDevice);

    dim3 thr(256);
    #define RED(dst, MN, Z, N, LD) \
        reduce_add<<<((MN) / 4 + 255) / 256, 256>>>(SL, dst, MN, Z, N, LD)

    // powers A^2 .. A^64 (doubling), split-K z=8
    gemm_sk<<<dim3(8,8,8), thr>>>(A,   A,   SL, 512, 512, 64, 512, 512); RED(P2,  262144, 8, 512, 512);
    gemm_sk<<<dim3(8,8,8), thr>>>(P2,  P2,  SL, 512, 512, 64, 512, 512); RED(P4,  262144, 8, 512, 512);
    gemm_sk<<<dim3(8,8,8), thr>>>(P4,  P4,  SL, 512, 512, 64, 512, 512); RED(P8,  262144, 8, 512, 512);
    gemm_sk<<<dim3(8,8,8), thr>>>(P8,  P8,  SL, 512, 512, 64, 512, 512); RED(P16, 262144, 8, 512, 512);
    gemm_sk<<<dim3(8,8,8), thr>>>(P16, P16, SL, 512, 512, 64, 512, 512); RED(P32, 262144, 8, 512, 512);
    gemm_sk<<<dim3(8,8,8), thr>>>(P32, P32, SL, 512, 512, 64, 512, 512); RED(P64, 262144, 8, 512, 512);
    // W stack: W_d = C A^d, d = 0..15
    gemm_sk<<<dim3(8,1,8), thr>>>(W, A,  SL,  64, 512, 64, 512, 512); RED(W + (size_t)64  * 512,  32768, 8, 512, 512);
    gemm_sk<<<dim3(8,2,8), thr>>>(W, P2, SL, 128, 512, 64, 512, 512); RED(W + (size_t)128 * 512,  65536, 8, 512, 512);
    gemm_sk<<<dim3(8,4,8), thr>>>(W, P4, SL, 256, 512, 64, 512, 512); RED(W + (size_t)256 * 512, 131072, 8, 512, 512);
    gemm_sk<<<dim3(8,8,8), thr>>>(W, P8, SL, 512, 512, 64, 512, 512); RED(W + (size_t)512 * 512, 262144, 8, 512, 512);
    // V stack: V_j = A^{16j} B (col blocks of width 64 in Vcat, ld=VW)
    gemm_sk<<<dim3(1,8,8), thr>>>(P16, V, SL, 512,  64, 64, 512, VW); RED(V + 64,  32768, 8,  64, VW);
    gemm_sk<<<dim3(2,8,8), thr>>>(P32, V, SL, 512, 128, 64, 512, VW); RED(V + 128, 65536, 8, 128, VW);
    gemm_sk<<<dim3(3,8,8), thr>>>(P64, V, SL, 512, 192, 64, 512, VW); RED(V + 256, 98304, 8, 192, VW);
    #undef RED

    // tap bank (fp16, B-operand layout, D folded into tap 0)
    k_assemble<<<DMAX, thr>>>(Dm);
    // tensor-core convolution (mma.sync fp16 + ldmatrix, fp32 accumulate)
    conv_tc<<<dim3(SEQ / TM, BATCH), 256, SM_TOTAL>>>(x, y);
}